// round 16
// baseline (speedup 1.0000x reference)
#include <cuda_runtime.h>
#include <cuda_bf16.h>
#include <math.h>
#include <stdint.h>

// Problem constants
constexpr int BATCH = 4;
constexpr int CH    = 256;
constexpr int NTOK  = 2304;    // 48*48
constexpr int NH    = 8;
constexpr int HD    = 32;
constexpr float SCALE2 = 0.17677669529663687f * 1.4426950408889634f; // 1/sqrt(32)*log2e

// ---------------------------------------------------------------------------
// bf16 hi/lo scratch (device globals: allocation-free)
// ---------------------------------------------------------------------------
__device__ __nv_bfloat16 g_xh[BATCH * CH * NTOK],  g_xl[BATCH * CH * NTOK];    // [b][c][p]
__device__ __nv_bfloat16 g_Wqh[3 * CH * CH],       g_Wql[3 * CH * CH];         // [o][c]
__device__ __nv_bfloat16 g_W0h[CH * CH],           g_W0l[CH * CH];
__device__ __nv_bfloat16 g_qkvh[BATCH * 3 * CH * NTOK], g_qkvl[BATCH * 3 * CH * NTOK]; // [b][o][p]
__device__ __nv_bfloat16 g_Oh[BATCH * CH * NTOK],  g_Ol[BATCH * CH * NTOK];    // [b][c][p]

// ---------------------------------------------------------------------------
// helpers
// ---------------------------------------------------------------------------
__device__ __forceinline__ uint32_t smem_u32(const void* p) {
    uint32_t a;
    asm("{ .reg .u64 t; cvta.to.shared.u64 t, %1; cvt.u32.u64 %0, t; }"
        : "=r"(a) : "l"(p));
    return a;
}
// fast pack: (f0,f1) -> bf16x2 hi {f1:f0} and residual lo
__device__ __forceinline__ void pack_hilo(float f0, float f1,
                                          uint32_t& h, uint32_t& l) {
    uint32_t hp;
    asm("cvt.rn.bf16x2.f32 %0, %1, %2;" : "=r"(hp) : "f"(f1), "f"(f0));
    float h0 = __uint_as_float(hp << 16);
    float h1 = __uint_as_float(hp & 0xffff0000u);
    h = hp;
    asm("cvt.rn.bf16x2.f32 %0, %1, %2;" : "=r"(l) : "f"(f1 - h1), "f"(f0 - h0));
}
__device__ __forceinline__ void split1(float f, __nv_bfloat16& h, __nv_bfloat16& l) {
    h = __float2bfloat16_rn(f);
    l = __float2bfloat16_rn(f - __bfloat162float(h));
}

#define MMA_BF16(d, a, b0, b1)                                            \
    asm volatile("mma.sync.aligned.m16n8k16.row.col.f32.bf16.bf16.f32 "   \
        "{%0,%1,%2,%3}, {%4,%5,%6,%7}, {%8,%9}, {%0,%1,%2,%3};"           \
        : "+f"((d)[0]), "+f"((d)[1]), "+f"((d)[2]), "+f"((d)[3])          \
        : "r"((a)[0]), "r"((a)[1]), "r"((a)[2]), "r"((a)[3]),             \
          "r"(b0), "r"(b1))

__device__ __forceinline__ void ldm_x4(uint32_t* r, uint32_t addr) {
    asm volatile("ldmatrix.sync.aligned.m8n8.x4.shared.b16 {%0,%1,%2,%3}, [%4];"
                 : "=r"(r[0]), "=r"(r[1]), "=r"(r[2]), "=r"(r[3]) : "r"(addr));
}
__device__ __forceinline__ void ldm_x4t(uint32_t* r, uint32_t addr) {
    asm volatile("ldmatrix.sync.aligned.m8n8.x4.trans.shared.b16 {%0,%1,%2,%3}, [%4];"
                 : "=r"(r[0]), "=r"(r[1]), "=r"(r[2]), "=r"(r[3]) : "r"(addr));
}
__device__ __forceinline__ void cp16(uint32_t s, const void* g) {
    asm volatile("cp.async.cg.shared.global [%0], [%1], 16;" :: "r"(s), "l"(g));
}
#define CP_COMMIT() asm volatile("cp.async.commit_group;" ::: "memory")
#define CP_WAIT1()  asm volatile("cp.async.wait_group 1;" ::: "memory")
#define CP_WAIT0()  asm volatile("cp.async.wait_group 0;" ::: "memory")

// ---------------------------------------------------------------------------
// Pre-split kernels: fp32 -> bf16 hi/lo
// ---------------------------------------------------------------------------
__global__ __launch_bounds__(256)
void split_x_kernel(const float* __restrict__ x)
{
    int i = blockIdx.x * 256 + threadIdx.x;   // float4 index
    float4 v = ((const float4*)x)[i];
    uint32_t h01, l01, h23, l23;
    pack_hilo(v.x, v.y, h01, l01);
    pack_hilo(v.z, v.w, h23, l23);
    ((uint32_t*)g_xh)[i * 2]     = h01;
    ((uint32_t*)g_xh)[i * 2 + 1] = h23;
    ((uint32_t*)g_xl)[i * 2]     = l01;
    ((uint32_t*)g_xl)[i * 2 + 1] = l23;
}

__global__ __launch_bounds__(256)
void split_w_kernel(const float* __restrict__ Wqkv, const float* __restrict__ W0)
{
    int i = blockIdx.x * 256 + threadIdx.x;   // float4 index
    const int NQ = 3 * CH * CH / 4;
    float4 v;
    uint32_t* dh;
    uint32_t* dl;
    int j;
    if (i < NQ) {
        v = ((const float4*)Wqkv)[i];
        dh = (uint32_t*)g_Wqh; dl = (uint32_t*)g_Wql; j = i;
    } else {
        v = ((const float4*)W0)[i - NQ];
        dh = (uint32_t*)g_W0h; dl = (uint32_t*)g_W0l; j = i - NQ;
    }
    uint32_t h01, l01, h23, l23;
    pack_hilo(v.x, v.y, h01, l01);
    pack_hilo(v.z, v.w, h23, l23);
    dh[j * 2] = h01; dh[j * 2 + 1] = h23;
    dl[j * 2] = l01; dl[j * 2 + 1] = l23;
}

// ---------------------------------------------------------------------------
// Epilogue functors
// ---------------------------------------------------------------------------
struct QkvEpi {   // write [b][o][p] bf16 hi/lo, coalesced; bias + Q-scale folded
    const float* bqkv;
    int b, o0, p0;
    __device__ __forceinline__ void operator()(float (*acc)[4], int w, int g, int c) const {
        #pragma unroll
        for (int rh = 0; rh < 2; rh++) {
            int og  = o0 + 16 * w + g + 8 * rh;
            int rem = og % 24;
            float scl  = ((rem >> 3) == 0) ? SCALE2 : 1.f;
            float bias = bqkv[og];
            size_t base = ((size_t)b * 3 * CH + og) * NTOK;
            #pragma unroll
            for (int nb = 0; nb < 16; nb++) {
                int p = p0 + 8 * nb + 2 * c;
                float f0 = (acc[nb][2 * rh]     + bias) * scl;
                float f1 = (acc[nb][2 * rh + 1] + bias) * scl;
                uint32_t h, l;
                pack_hilo(f0, f1, h, l);
                *(uint32_t*)&g_qkvh[base + p] = h;
                *(uint32_t*)&g_qkvl[base + p] = l;
            }
        }
    }
};

struct ProjEpi {
    const float* b0;
    float* out;
    int b, o0, p0;
    __device__ __forceinline__ void operator()(float (*acc)[4], int w, int g, int c) const {
        #pragma unroll
        for (int rh = 0; rh < 2; rh++) {
            int og = o0 + 16 * w + g + 8 * rh;
            float bias = b0[og];
            float* dst = out + (size_t)(b * CH + og) * NTOK;
            #pragma unroll
            for (int nb = 0; nb < 16; nb++) {
                int p = p0 + 8 * nb + 2 * c;
                float2 v = make_float2(acc[nb][2 * rh] + bias,
                                       acc[nb][2 * rh + 1] + bias);
                *(float2*)(dst + p) = v;
            }
        }
    }
};

// ---------------------------------------------------------------------------
// bf16 GEMM core (R11/R12 winner, verbatim): C[128o x 128p], K=256.
// Static single-buffer smem (37.9 KB, 2 CTAs/SM), cp.async fills.
// ---------------------------------------------------------------------------
constexpr int GW_STR = 40;
constexpr int GX_STR = 136;

template <typename EPI>
__device__ __forceinline__ void gemm_core(
    const __nv_bfloat16* __restrict__ wh, const __nv_bfloat16* __restrict__ wl, int wld,
    const __nv_bfloat16* __restrict__ xh, const __nv_bfloat16* __restrict__ xl, int bld,
    int o0, int p0, const EPI& epi)
{
    __shared__ __nv_bfloat16 Wh[128 * GW_STR];
    __shared__ __nv_bfloat16 Wl[128 * GW_STR];
    __shared__ __nv_bfloat16 Xh[32 * GX_STR];
    __shared__ __nv_bfloat16 Xl[32 * GX_STR];

    const int tid  = threadIdx.x;
    const int w    = tid >> 5;
    const int lane = tid & 31;
    const int L    = lane;

    const uint32_t whb = smem_u32(Wh), wlb = smem_u32(Wl);
    const uint32_t xhb = smem_u32(Xh), xlb = smem_u32(Xl);
    const uint32_t aoff = (uint32_t)((16 * w + (L & 7) + 8 * ((L >> 3) & 1)) * GW_STR
                                     + 8 * (L >> 4)) * 2;
    const uint32_t boff = (uint32_t)(L * GX_STR) * 2;

    float acc[16][4];
    #pragma unroll
    for (int i = 0; i < 16; i++)
        #pragma unroll
        for (int j = 0; j < 4; j++) acc[i][j] = 0.f;

    for (int kb = 0; kb < 8; kb++) {
        const int k0 = kb * 32;
        __syncthreads();
        #pragma unroll
        for (int v = 0; v < 2; v++) {
            int cch = tid * 2 + v;
            int row = cch >> 2, q = cch & 3;
            size_t go = (size_t)(o0 + row) * wld + k0 + q * 8;
            uint32_t soff = (uint32_t)(row * GW_STR + q * 8) * 2;
            cp16(whb + soff, wh + go);
            cp16(wlb + soff, wl + go);
        }
        #pragma unroll
        for (int v = 0; v < 2; v++) {
            int cch = tid * 2 + v;
            int row = cch >> 4, q = cch & 15;
            size_t go = (size_t)(k0 + row) * bld + p0 + q * 8;
            uint32_t soff = (uint32_t)(row * GX_STR + q * 8) * 2;
            cp16(xhb + soff, xh + go);
            cp16(xlb + soff, xl + go);
        }
        CP_COMMIT();
        CP_WAIT0();
        __syncthreads();

        uint32_t ah0[4], ah1[4], al0[4], al1[4];
        ldm_x4(ah0, whb + aoff);
        ldm_x4(ah1, whb + aoff + 32);
        ldm_x4(al0, wlb + aoff);
        ldm_x4(al1, wlb + aoff + 32);

        #pragma unroll
        for (int nb = 0; nb < 16; nb++) {
            uint32_t bh[4], bl[4];
            ldm_x4t(bh, xhb + boff + nb * 16);
            ldm_x4t(bl, xlb + boff + nb * 16);
            float* d = acc[nb];
            MMA_BF16(d, ah0, bh[0], bh[1]);
            MMA_BF16(d, ah1, bh[2], bh[3]);
            MMA_BF16(d, al0, bh[0], bh[1]);
            MMA_BF16(d, al1, bh[2], bh[3]);
            MMA_BF16(d, ah0, bl[0], bl[1]);
            MMA_BF16(d, ah1, bl[2], bl[3]);
        }
    }
    epi(acc, w, lane >> 2, lane & 3);
}

__global__ __launch_bounds__(256)
void qkv_kernel(const float* __restrict__ bqkv)
{
    const int p0 = blockIdx.x * 128;
    const int o0 = blockIdx.y * 128;
    const int b  = blockIdx.z;
    QkvEpi epi{bqkv, b, o0, p0};
    gemm_core(g_Wqh, g_Wql, CH,
              g_xh + (size_t)b * CH * NTOK, g_xl + (size_t)b * CH * NTOK, NTOK,
              o0, p0, epi);
}

__global__ __launch_bounds__(256)
void proj_kernel(const float* __restrict__ b0, float* __restrict__ out)
{
    const int p0 = blockIdx.x * 128;
    const int o0 = blockIdx.y * 128;
    const int b  = blockIdx.z;
    ProjEpi epi{b0, out, b, o0, p0};
    gemm_core(g_W0h, g_W0l, CH,
              g_Oh + (size_t)b * CH * NTOK, g_Ol + (size_t)b * CH * NTOK, NTOK,
              o0, p0, epi);
}

// ---------------------------------------------------------------------------
// Kernel 2: flash attention. BQ=128, 256 threads, 2 CTAs/SM (independent
// phases), 2-stage cp.async double buffer (69.6 KB dynamic smem per CTA).
// Inner pipeline identical to the R12 winner.
// ---------------------------------------------------------------------------
constexpr int AK2   = 136;                  // d-row stride (bf16 units)
constexpr int A_ARR = 32 * AK2;             // 4352 units per array
constexpr int A_ARR_B   = A_ARR * 2;        // 8704 bytes
constexpr int A_STAGE_B = 4 * A_ARR_B;      // 34816 bytes
constexpr int ATTN_SMEM = A_STAGE_B * 2;    // 69632 bytes

__global__ __launch_bounds__(256, 2)
void attn_kernel()
{
    extern __shared__ __nv_bfloat16 smA[];

    const int tid  = threadIdx.x;
    const int w    = tid >> 5;          // 0..7
    const int lane = tid & 31;
    const int g    = lane >> 2;
    const int c    = lane & 3;
    const int L    = lane;

    const int q0 = blockIdx.x * 128;
    const int bm = blockIdx.y;
    const int b  = bm >> 3, m = bm & 7;
    const size_t obase = (size_t)b * 3 * CH * NTOK;

    const uint32_t sb = smem_u32(smA);

    const uint32_t kfrag = (uint32_t)((((L >> 3) & 1) * 8 + (L & 7)) * AK2
                                      + (L >> 4) * 8) * 2;
    const uint32_t vfrag = (uint32_t)(((L >> 4) * 8 + (L & 7)) * AK2
                                      + ((L >> 3) & 1) * 8) * 2;

    // Q fragments from [o][p]: row = d*24 + m (pre-scaled)
    uint32_t qh[2][4], ql[2][4];
    {
        const int r0 = q0 + 16 * w + g;
        #pragma unroll
        for (int ks = 0; ks < 2; ks++) {
            #pragma unroll
            for (int o8 = 0; o8 < 2; o8++) {
                int d0 = 16 * ks + 8 * o8 + 2 * c;
                size_t row0 = obase + (size_t)(d0 * 24 + m) * NTOK;
                size_t row1 = obase + (size_t)((d0 + 1) * 24 + m) * NTOK;
                #pragma unroll
                for (int rh = 0; rh < 2; rh++) {
                    int q = r0 + 8 * rh;
                    uint32_t h0 = *(const uint16_t*)&g_qkvh[row0 + q];
                    uint32_t h1 = *(const uint16_t*)&g_qkvh[row1 + q];
                    uint32_t l0 = *(const uint16_t*)&g_qkvl[row0 + q];
                    uint32_t l1 = *(const uint16_t*)&g_qkvl[row1 + q];
                    qh[ks][o8 * 2 + rh] = h0 | (h1 << 16);
                    ql[ks][o8 * 2 + rh] = l0 | (l1 << 16);
                }
            }
        }
    }

    float oacc[4][4];
    #pragma unroll
    for (int i = 0; i < 4; i++)
        #pragma unroll
        for (int j = 0; j < 4; j++) oacc[i][j] = 0.f;
    float rs0 = 0.f, rs1 = 0.f;

    // fill one 128-key stage: 512 chunks per array over 256 threads
    auto fill = [&](int stage, int t) {
        const int kt = t * 128;
        const uint32_t s0 = sb + (uint32_t)stage * A_STAGE_B;
        #pragma unroll
        for (int v = 0; v < 2; v++) {
            int cch = tid * 2 + v;
            int d = cch >> 4, kq = (cch & 15) * 8;
            const uint32_t soff = (uint32_t)(d * AK2 + kq) * 2;
            const int ko = kt + kq;
            cp16(s0 + soff,                 g_qkvh + obase + (size_t)(d * 24 + 8 + m)  * NTOK + ko);
            cp16(s0 + A_ARR_B + soff,       g_qkvl + obase + (size_t)(d * 24 + 8 + m)  * NTOK + ko);
            cp16(s0 + 2 * A_ARR_B + soff,   g_qkvh + obase + (size_t)(d * 24 + 16 + m) * NTOK + ko);
            cp16(s0 + 3 * A_ARR_B + soff,   g_qkvl + obase + (size_t)(d * 24 + 16 + m) * NTOK + ko);
        }
        CP_COMMIT();
    };

    fill(0, 0);
    for (int t = 0; t < 18; t++) {
        if (t < 17) { fill((t + 1) & 1, t + 1); CP_WAIT1(); }
        else        { CP_WAIT0(); }
        __syncthreads();

        const uint32_t s0  = sb + (uint32_t)(t & 1) * A_STAGE_B;
        const uint32_t khb = s0;
        const uint32_t klb = s0 + A_ARR_B;
        const uint32_t vhb = s0 + 2 * A_ARR_B;
        const uint32_t vlb = s0 + 3 * A_ARR_B;

        #pragma unroll
        for (int ks = 0; ks < 8; ks++) {
            const uint32_t toff = (uint32_t)ks * 32;   // 16 keys * 2B

            uint32_t vh0[4], vh1[4], vl0[4], vl1[4];
            ldm_x4(vh0, vhb + vfrag + toff);
            ldm_x4(vh1, vhb + vfrag + toff + 16 * AK2 * 2);
            ldm_x4(vl0, vlb + vfrag + toff);
            ldm_x4(vl1, vlb + vfrag + toff + 16 * AK2 * 2);

            uint32_t bh0[4], bh1[4], bl0[4], bl1[4];
            ldm_x4t(bh0, khb + kfrag + toff);
            ldm_x4t(bh1, khb + kfrag + toff + 16 * AK2 * 2);
            ldm_x4t(bl0, klb + kfrag + toff);
            ldm_x4t(bl1, klb + kfrag + toff + 16 * AK2 * 2);

            float s0a[4] = {0.f, 0.f, 0.f, 0.f};
            float s0b[4] = {0.f, 0.f, 0.f, 0.f};
            float s1a[4] = {0.f, 0.f, 0.f, 0.f};
            float s1b[4] = {0.f, 0.f, 0.f, 0.f};
            MMA_BF16(s0a, qh[0], bh0[0], bh0[1]);
            MMA_BF16(s0b, qh[1], bh1[0], bh1[1]);
            MMA_BF16(s0a, ql[0], bh0[0], bh0[1]);
            MMA_BF16(s0b, ql[1], bh1[0], bh1[1]);
            MMA_BF16(s0a, qh[0], bl0[0], bl0[1]);
            MMA_BF16(s0b, qh[1], bl1[0], bl1[1]);
            MMA_BF16(s1a, qh[0], bh0[2], bh0[3]);
            MMA_BF16(s1b, qh[1], bh1[2], bh1[3]);
            MMA_BF16(s1a, ql[0], bh0[2], bh0[3]);
            MMA_BF16(s1b, ql[1], bh1[2], bh1[3]);
            MMA_BF16(s1a, qh[0], bl0[2], bl0[3]);
            MMA_BF16(s1b, qh[1], bl1[2], bl1[3]);

            float s0v[4], s1v[4];
            #pragma unroll
            for (int i = 0; i < 4; i++) {
                s0v[i] = exp2f(s0a[i] + s0b[i]);
                s1v[i] = exp2f(s1a[i] + s1b[i]);
            }
            rs0 += s0v[0] + s0v[1] + s1v[0] + s1v[1];
            rs1 += s0v[2] + s0v[3] + s1v[2] + s1v[3];

            uint32_t ah[4], al[4];
            pack_hilo(s0v[0], s0v[1], ah[0], al[0]);
            pack_hilo(s0v[2], s0v[3], ah[1], al[1]);
            pack_hilo(s1v[0], s1v[1], ah[2], al[2]);
            pack_hilo(s1v[2], s1v[3], ah[3], al[3]);

            MMA_BF16(oacc[0], ah, vh0[0], vh0[1]);
            MMA_BF16(oacc[1], ah, vh0[2], vh0[3]);
            MMA_BF16(oacc[2], ah, vh1[0], vh1[1]);
            MMA_BF16(oacc[3], ah, vh1[2], vh1[3]);
            MMA_BF16(oacc[0], al, vh0[0], vh0[1]);
            MMA_BF16(oacc[1], al, vh0[2], vh0[3]);
            MMA_BF16(oacc[2], al, vh1[0], vh1[1]);
            MMA_BF16(oacc[3], al, vh1[2], vh1[3]);
            MMA_BF16(oacc[0], ah, vl0[0], vl0[1]);
            MMA_BF16(oacc[1], ah, vl0[2], vl0[3]);
            MMA_BF16(oacc[2], ah, vl1[0], vl1[1]);
            MMA_BF16(oacc[3], ah, vl1[2], vl1[3]);
        }
        __syncthreads();
    }

    // epilogue: reduce sums, transpose O through smem, write [c][p] coalesced
    rs0 += __shfl_xor_sync(0xffffffffu, rs0, 1);
    rs0 += __shfl_xor_sync(0xffffffffu, rs0, 2);
    rs1 += __shfl_xor_sync(0xffffffffu, rs1, 1);
    rs1 += __shfl_xor_sync(0xffffffffu, rs1, 2);
    const float inv0 = 1.f / rs0;
    const float inv1 = 1.f / rs1;

    float* Osm = (float*)smA;               // [32 d][132 q-pad] = 16.9 KB
    const int qloc = 16 * w + g;
    #pragma unroll
    for (int nv = 0; nv < 4; nv++) {
        #pragma unroll
        for (int cc = 0; cc < 2; cc++) {
            int d = 8 * nv + 2 * c + cc;
            Osm[d * 132 + qloc]     = oacc[nv][cc]     * inv0;
            Osm[d * 132 + qloc + 8] = oacc[nv][2 + cc] * inv1;
        }
    }
    __syncthreads();
    {
        int d  = tid >> 3;            // 0..31
        int qc = (tid & 7) * 16;      // 0..112
        __nv_bfloat16 hbuf[16], lbuf[16];
        #pragma unroll
        for (int i = 0; i < 16; i++)
            split1(Osm[d * 132 + qc + i], hbuf[i], lbuf[i]);
        size_t dst = (size_t)(b * CH + m * HD + d) * NTOK + q0 + qc;
        *(uint4*)&g_Oh[dst]     = *(uint4*)&hbuf[0];
        *(uint4*)&g_Oh[dst + 8] = *(uint4*)&hbuf[8];
        *(uint4*)&g_Ol[dst]     = *(uint4*)&lbuf[0];
        *(uint4*)&g_Ol[dst + 8] = *(uint4*)&lbuf[8];
    }
}

// ---------------------------------------------------------------------------
extern "C" void kernel_launch(void* const* d_in, const int* in_sizes, int n_in,
                              void* d_out, int out_size)
{
    (void)in_sizes; (void)n_in; (void)out_size;
    const float* x    = (const float*)d_in[0];
    const float* Wqkv = (const float*)d_in[1];
    const float* bqkv = (const float*)d_in[2];
    const float* W0   = (const float*)d_in[3];
    const float* b0   = (const float*)d_in[4];
    float* out = (float*)d_out;

    cudaFuncSetAttribute(attn_kernel, cudaFuncAttributeMaxDynamicSharedMemorySize, ATTN_SMEM);

    split_x_kernel<<<BATCH * CH * NTOK / 1024, 256>>>(x);
    split_w_kernel<<<(3 * CH * CH + CH * CH) / 1024, 256>>>(Wqkv, W0);
    qkv_kernel<<<dim3(NTOK / 128, (3 * CH) / 128, BATCH), 256>>>(bqkv);
    attn_kernel<<<dim3(NTOK / 128, BATCH * NH), 256, ATTN_SMEM>>>();
    proj_kernel<<<dim3(NTOK / 128, CH / 128, BATCH), 256>>>(b0, out);
}

// round 17
// speedup vs baseline: 1.0780x; 1.0780x over previous
#include <cuda_runtime.h>
#include <cuda_bf16.h>
#include <math.h>
#include <stdint.h>

// Problem constants
constexpr int BATCH = 4;
constexpr int CH    = 256;
constexpr int NTOK  = 2304;    // 48*48
constexpr int NH    = 8;
constexpr int HD    = 32;
constexpr float SCALE2 = 0.17677669529663687f * 1.4426950408889634f; // 1/sqrt(32)*log2e

// ---------------------------------------------------------------------------
// bf16 hi/lo scratch (device globals: allocation-free)
// ---------------------------------------------------------------------------
__device__ __nv_bfloat16 g_xh[BATCH * CH * NTOK],  g_xl[BATCH * CH * NTOK];    // [b][c][p]
__device__ __nv_bfloat16 g_Wqh[3 * CH * CH],       g_Wql[3 * CH * CH];         // [o][c]
__device__ __nv_bfloat16 g_W0h[CH * CH],           g_W0l[CH * CH];
__device__ __nv_bfloat16 g_qkvh[BATCH * 3 * CH * NTOK], g_qkvl[BATCH * 3 * CH * NTOK]; // [b][o][p]
__device__ __nv_bfloat16 g_Oh[BATCH * CH * NTOK],  g_Ol[BATCH * CH * NTOK];    // [b][c][p]

// ---------------------------------------------------------------------------
// helpers
// ---------------------------------------------------------------------------
__device__ __forceinline__ uint32_t smem_u32(const void* p) {
    uint32_t a;
    asm("{ .reg .u64 t; cvta.to.shared.u64 t, %1; cvt.u32.u64 %0, t; }"
        : "=r"(a) : "l"(p));
    return a;
}
// fast pack: (f0,f1) -> bf16x2 hi {f1:f0} and residual lo
__device__ __forceinline__ void pack_hilo(float f0, float f1,
                                          uint32_t& h, uint32_t& l) {
    uint32_t hp;
    asm("cvt.rn.bf16x2.f32 %0, %1, %2;" : "=r"(hp) : "f"(f1), "f"(f0));
    float h0 = __uint_as_float(hp << 16);
    float h1 = __uint_as_float(hp & 0xffff0000u);
    h = hp;
    asm("cvt.rn.bf16x2.f32 %0, %1, %2;" : "=r"(l) : "f"(f1 - h1), "f"(f0 - h0));
}
__device__ __forceinline__ void split1(float f, __nv_bfloat16& h, __nv_bfloat16& l) {
    h = __float2bfloat16_rn(f);
    l = __float2bfloat16_rn(f - __bfloat162float(h));
}

#define MMA_BF16(d, a, b0, b1)                                            \
    asm volatile("mma.sync.aligned.m16n8k16.row.col.f32.bf16.bf16.f32 "   \
        "{%0,%1,%2,%3}, {%4,%5,%6,%7}, {%8,%9}, {%0,%1,%2,%3};"           \
        : "+f"((d)[0]), "+f"((d)[1]), "+f"((d)[2]), "+f"((d)[3])          \
        : "r"((a)[0]), "r"((a)[1]), "r"((a)[2]), "r"((a)[3]),             \
          "r"(b0), "r"(b1))

__device__ __forceinline__ void ldm_x4(uint32_t* r, uint32_t addr) {
    asm volatile("ldmatrix.sync.aligned.m8n8.x4.shared.b16 {%0,%1,%2,%3}, [%4];"
                 : "=r"(r[0]), "=r"(r[1]), "=r"(r[2]), "=r"(r[3]) : "r"(addr));
}
__device__ __forceinline__ void ldm_x4t(uint32_t* r, uint32_t addr) {
    asm volatile("ldmatrix.sync.aligned.m8n8.x4.trans.shared.b16 {%0,%1,%2,%3}, [%4];"
                 : "=r"(r[0]), "=r"(r[1]), "=r"(r[2]), "=r"(r[3]) : "r"(addr));
}
__device__ __forceinline__ void cp16(uint32_t s, const void* g) {
    asm volatile("cp.async.cg.shared.global [%0], [%1], 16;" :: "r"(s), "l"(g));
}
#define CP_COMMIT() asm volatile("cp.async.commit_group;" ::: "memory")
#define CP_WAIT1()  asm volatile("cp.async.wait_group 1;" ::: "memory")
#define CP_WAIT0()  asm volatile("cp.async.wait_group 0;" ::: "memory")

// ---------------------------------------------------------------------------
// Pre-split kernels: fp32 -> bf16 hi/lo
// ---------------------------------------------------------------------------
__global__ __launch_bounds__(256)
void split_x_kernel(const float* __restrict__ x)
{
    int i = blockIdx.x * 256 + threadIdx.x;   // float4 index
    float4 v = ((const float4*)x)[i];
    uint32_t h01, l01, h23, l23;
    pack_hilo(v.x, v.y, h01, l01);
    pack_hilo(v.z, v.w, h23, l23);
    ((uint32_t*)g_xh)[i * 2]     = h01;
    ((uint32_t*)g_xh)[i * 2 + 1] = h23;
    ((uint32_t*)g_xl)[i * 2]     = l01;
    ((uint32_t*)g_xl)[i * 2 + 1] = l23;
}

__global__ __launch_bounds__(256)
void split_w_kernel(const float* __restrict__ Wqkv, const float* __restrict__ W0)
{
    int i = blockIdx.x * 256 + threadIdx.x;   // float4 index
    const int NQ = 3 * CH * CH / 4;
    float4 v;
    uint32_t* dh;
    uint32_t* dl;
    int j;
    if (i < NQ) {
        v = ((const float4*)Wqkv)[i];
        dh = (uint32_t*)g_Wqh; dl = (uint32_t*)g_Wql; j = i;
    } else {
        v = ((const float4*)W0)[i - NQ];
        dh = (uint32_t*)g_W0h; dl = (uint32_t*)g_W0l; j = i - NQ;
    }
    uint32_t h01, l01, h23, l23;
    pack_hilo(v.x, v.y, h01, l01);
    pack_hilo(v.z, v.w, h23, l23);
    dh[j * 2] = h01; dh[j * 2 + 1] = h23;
    dl[j * 2] = l01; dl[j * 2 + 1] = l23;
}

// ---------------------------------------------------------------------------
// Epilogue functors (gemm: o-warp wo 0..3, p-half wp 0..1, 8 n-blocks)
// ---------------------------------------------------------------------------
struct QkvEpi {
    const float* bqkv;
    int b, o0, p0;
    __device__ __forceinline__ void operator()(float (*acc)[4], int wo, int wp,
                                               int g, int c) const {
        #pragma unroll
        for (int rh = 0; rh < 2; rh++) {
            int og  = o0 + 16 * wo + g + 8 * rh;
            int rem = og % 24;
            float scl  = ((rem >> 3) == 0) ? SCALE2 : 1.f;
            float bias = bqkv[og];
            size_t base = ((size_t)b * 3 * CH + og) * NTOK;
            #pragma unroll
            for (int nb = 0; nb < 8; nb++) {
                int p = p0 + wp * 64 + 8 * nb + 2 * c;
                float f0 = (acc[nb][2 * rh]     + bias) * scl;
                float f1 = (acc[nb][2 * rh + 1] + bias) * scl;
                uint32_t h, l;
                pack_hilo(f0, f1, h, l);
                *(uint32_t*)&g_qkvh[base + p] = h;
                *(uint32_t*)&g_qkvl[base + p] = l;
            }
        }
    }
};

struct ProjEpi {
    const float* b0;
    float* out;
    int b, o0, p0;
    __device__ __forceinline__ void operator()(float (*acc)[4], int wo, int wp,
                                               int g, int c) const {
        #pragma unroll
        for (int rh = 0; rh < 2; rh++) {
            int og = o0 + 16 * wo + g + 8 * rh;
            float bias = b0[og];
            float* dst = out + (size_t)(b * CH + og) * NTOK;
            #pragma unroll
            for (int nb = 0; nb < 8; nb++) {
                int p = p0 + wp * 64 + 8 * nb + 2 * c;
                float2 v = make_float2(acc[nb][2 * rh] + bias,
                                       acc[nb][2 * rh + 1] + bias);
                *(float2*)(dst + p) = v;
            }
        }
    }
};

// ---------------------------------------------------------------------------
// bf16 GEMM core: C[64o x 128p] = A[o,c]*B[c,p], K=256, hi/lo 3-term.
// 256 thr (warp = wo 0..3 x wp 0..1), 2-stage cp.async double buffer,
// 55.3 KB dynamic smem -> 2 CTAs/SM (occupancy + prefetch overlap).
// Per-stage bytes: Wh@0 (5120), Wl@5120, Xh@10240 (8704), Xl@18944; stage 27648.
// ---------------------------------------------------------------------------
constexpr int GW_STR = 40;
constexpr int GX_STR = 136;
constexpr int G_STAGE_B = 64 * GW_STR * 2 * 2 + 32 * GX_STR * 2 * 2;  // 27648
constexpr int GEMM_SMEM = G_STAGE_B * 2;                              // 55296

template <typename EPI>
__device__ __forceinline__ void gemm_core(
    const __nv_bfloat16* __restrict__ wh, const __nv_bfloat16* __restrict__ wl, int wld,
    const __nv_bfloat16* __restrict__ xh, const __nv_bfloat16* __restrict__ xl, int bld,
    int o0, int p0, const EPI& epi)
{
    extern __shared__ __nv_bfloat16 smg[];
    const int tid  = threadIdx.x;
    const int w    = tid >> 5;      // 0..7
    const int wo   = w & 3;
    const int wp   = w >> 2;
    const int lane = tid & 31;
    const int L    = lane;
    const uint32_t sb = smem_u32(smg);

    const uint32_t aoff = (uint32_t)((16 * wo + (L & 7) + 8 * ((L >> 3) & 1)) * GW_STR
                                     + 8 * (L >> 4)) * 2;
    const uint32_t boff = (uint32_t)(L * GX_STR + wp * 64) * 2;

    auto fill = [&](int stage, int kb) {
        const int k0 = kb * 32;
        const uint32_t s0 = sb + (uint32_t)stage * G_STAGE_B;
        {   // W tiles: 64 rows x 4 chunks = 256 per array; 1 per thread over 2 arrays
            int row = tid >> 2, q = tid & 3;   // rows 0..63 (tid<256: row<64)
            size_t go = (size_t)(o0 + row) * wld + k0 + q * 8;
            uint32_t soff = (uint32_t)(row * GW_STR + q * 8) * 2;
            cp16(s0 + soff,        wh + go);
            cp16(s0 + 5120 + soff, wl + go);
        }
        #pragma unroll
        for (int v = 0; v < 2; v++) {   // X tiles: 512 chunks per array
            int cch = tid * 2 + v;
            int row = cch >> 4, q = cch & 15;
            size_t go = (size_t)(k0 + row) * bld + p0 + q * 8;
            uint32_t soff = (uint32_t)(row * GX_STR + q * 8) * 2;
            cp16(s0 + 10240 + soff, xh + go);
            cp16(s0 + 18944 + soff, xl + go);
        }
        CP_COMMIT();
    };

    float acc[8][4];
    #pragma unroll
    for (int i = 0; i < 8; i++)
        #pragma unroll
        for (int j = 0; j < 4; j++) acc[i][j] = 0.f;

    fill(0, 0);
    for (int kb = 0; kb < 8; kb++) {
        if (kb < 7) { fill((kb + 1) & 1, kb + 1); CP_WAIT1(); }
        else        { CP_WAIT0(); }
        __syncthreads();

        const uint32_t s0  = sb + (uint32_t)(kb & 1) * G_STAGE_B;
        const uint32_t whb = s0,          wlb = s0 + 5120;
        const uint32_t xhb = s0 + 10240,  xlb = s0 + 18944;

        uint32_t ah0[4], ah1[4], al0[4], al1[4];
        ldm_x4(ah0, whb + aoff);
        ldm_x4(ah1, whb + aoff + 32);
        ldm_x4(al0, wlb + aoff);
        ldm_x4(al1, wlb + aoff + 32);

        #pragma unroll
        for (int nb = 0; nb < 8; nb++) {
            uint32_t bh[4], bl[4];
            ldm_x4t(bh, xhb + boff + nb * 16);
            ldm_x4t(bl, xlb + boff + nb * 16);
            float* d = acc[nb];
            MMA_BF16(d, ah0, bh[0], bh[1]);
            MMA_BF16(d, ah1, bh[2], bh[3]);
            MMA_BF16(d, al0, bh[0], bh[1]);
            MMA_BF16(d, al1, bh[2], bh[3]);
            MMA_BF16(d, ah0, bl[0], bl[1]);
            MMA_BF16(d, ah1, bl[2], bl[3]);
        }
        __syncthreads();
    }
    epi(acc, wo, wp, lane >> 2, lane & 3);
}

__global__ __launch_bounds__(256, 2)
void qkv_kernel(const float* __restrict__ bqkv)
{
    const int p0 = blockIdx.x * 128;
    const int o0 = blockIdx.y * 64;
    const int b  = blockIdx.z;
    QkvEpi epi{bqkv, b, o0, p0};
    gemm_core(g_Wqh, g_Wql, CH,
              g_xh + (size_t)b * CH * NTOK, g_xl + (size_t)b * CH * NTOK, NTOK,
              o0, p0, epi);
}

__global__ __launch_bounds__(256, 2)
void proj_kernel(const float* __restrict__ b0, float* __restrict__ out)
{
    const int p0 = blockIdx.x * 128;
    const int o0 = blockIdx.y * 64;
    const int b  = blockIdx.z;
    ProjEpi epi{b0, out, b, o0, p0};
    gemm_core(g_W0h, g_W0l, CH,
              g_Oh + (size_t)b * CH * NTOK, g_Ol + (size_t)b * CH * NTOK, NTOK,
              o0, p0, epi);
}

// ---------------------------------------------------------------------------
// Kernel 2: flash attention (R12 winner, verbatim). BQ=256 (512 thr),
// 2-stage cp.async double buffer (69.6 KB), V-early, no phase rotation.
// ---------------------------------------------------------------------------
constexpr int AK2   = 136;                  // d-row stride (bf16 units)
constexpr int A_ARR = 32 * AK2;             // 4352 units per array
constexpr int A_ARR_B   = A_ARR * 2;        // 8704 bytes
constexpr int A_STAGE_B = 4 * A_ARR_B;      // 34816 bytes
constexpr int ATTN_SMEM = A_STAGE_B * 2;    // 69632 bytes

__global__ __launch_bounds__(512, 1)
void attn_kernel()
{
    extern __shared__ __nv_bfloat16 smA[];

    const int tid  = threadIdx.x;
    const int w    = tid >> 5;          // 0..15
    const int lane = tid & 31;
    const int g    = lane >> 2;
    const int c    = lane & 3;
    const int L    = lane;

    const int q0 = blockIdx.x * 256;
    const int bm = blockIdx.y;
    const int b  = bm >> 3, m = bm & 7;
    const size_t obase = (size_t)b * 3 * CH * NTOK;

    const uint32_t sb = smem_u32(smA);

    const uint32_t kfrag = (uint32_t)((((L >> 3) & 1) * 8 + (L & 7)) * AK2
                                      + (L >> 4) * 8) * 2;
    const uint32_t vfrag = (uint32_t)(((L >> 4) * 8 + (L & 7)) * AK2
                                      + ((L >> 3) & 1) * 8) * 2;

    // Q fragments from [o][p]: row = d*24 + m (pre-scaled)
    uint32_t qh[2][4], ql[2][4];
    {
        const int r0 = q0 + 16 * w + g;
        #pragma unroll
        for (int ks = 0; ks < 2; ks++) {
            #pragma unroll
            for (int o8 = 0; o8 < 2; o8++) {
                int d0 = 16 * ks + 8 * o8 + 2 * c;
                size_t row0 = obase + (size_t)(d0 * 24 + m) * NTOK;
                size_t row1 = obase + (size_t)((d0 + 1) * 24 + m) * NTOK;
                #pragma unroll
                for (int rh = 0; rh < 2; rh++) {
                    int q = r0 + 8 * rh;
                    uint32_t h0 = *(const uint16_t*)&g_qkvh[row0 + q];
                    uint32_t h1 = *(const uint16_t*)&g_qkvh[row1 + q];
                    uint32_t l0 = *(const uint16_t*)&g_qkvl[row0 + q];
                    uint32_t l1 = *(const uint16_t*)&g_qkvl[row1 + q];
                    qh[ks][o8 * 2 + rh] = h0 | (h1 << 16);
                    ql[ks][o8 * 2 + rh] = l0 | (l1 << 16);
                }
            }
        }
    }

    float oacc[4][4];
    #pragma unroll
    for (int i = 0; i < 4; i++)
        #pragma unroll
        for (int j = 0; j < 4; j++) oacc[i][j] = 0.f;
    float rs0 = 0.f, rs1 = 0.f;

    auto fill = [&](int stage, int t) {
        const int kt = t * 128;
        const uint32_t s0 = sb + (uint32_t)stage * A_STAGE_B;
        const int d  = tid >> 4;
        const int kq = (tid & 15) * 8;
        const uint32_t soff = (uint32_t)(d * AK2 + kq) * 2;
        cp16(s0 + soff,                 g_qkvh + obase + (size_t)(d * 24 + 8 + m)  * NTOK + kt + kq);
        cp16(s0 + A_ARR_B + soff,       g_qkvl + obase + (size_t)(d * 24 + 8 + m)  * NTOK + kt + kq);
        cp16(s0 + 2 * A_ARR_B + soff,   g_qkvh + obase + (size_t)(d * 24 + 16 + m) * NTOK + kt + kq);
        cp16(s0 + 3 * A_ARR_B + soff,   g_qkvl + obase + (size_t)(d * 24 + 16 + m) * NTOK + kt + kq);
        CP_COMMIT();
    };

    fill(0, 0);
    for (int t = 0; t < 18; t++) {
        if (t < 17) { fill((t + 1) & 1, t + 1); CP_WAIT1(); }
        else        { CP_WAIT0(); }
        __syncthreads();

        const uint32_t s0  = sb + (uint32_t)(t & 1) * A_STAGE_B;
        const uint32_t khb = s0;
        const uint32_t klb = s0 + A_ARR_B;
        const uint32_t vhb = s0 + 2 * A_ARR_B;
        const uint32_t vlb = s0 + 3 * A_ARR_B;

        #pragma unroll
        for (int ks = 0; ks < 8; ks++) {
            const uint32_t toff = (uint32_t)ks * 32;   // 16 keys * 2B

            uint32_t vh0[4], vh1[4], vl0[4], vl1[4];
            ldm_x4(vh0, vhb + vfrag + toff);
            ldm_x4(vh1, vhb + vfrag + toff + 16 * AK2 * 2);
            ldm_x4(vl0, vlb + vfrag + toff);
            ldm_x4(vl1, vlb + vfrag + toff + 16 * AK2 * 2);

            uint32_t bh0[4], bh1[4], bl0[4], bl1[4];
            ldm_x4t(bh0, khb + kfrag + toff);
            ldm_x4t(bh1, khb + kfrag + toff + 16 * AK2 * 2);
            ldm_x4t(bl0, klb + kfrag + toff);
            ldm_x4t(bl1, klb + kfrag + toff + 16 * AK2 * 2);

            float s0a[4] = {0.f, 0.f, 0.f, 0.f};
            float s0b[4] = {0.f, 0.f, 0.f, 0.f};
            float s1a[4] = {0.f, 0.f, 0.f, 0.f};
            float s1b[4] = {0.f, 0.f, 0.f, 0.f};
            MMA_BF16(s0a, qh[0], bh0[0], bh0[1]);
            MMA_BF16(s0b, qh[1], bh1[0], bh1[1]);
            MMA_BF16(s0a, ql[0], bh0[0], bh0[1]);
            MMA_BF16(s0b, ql[1], bh1[0], bh1[1]);
            MMA_BF16(s0a, qh[0], bl0[0], bl0[1]);
            MMA_BF16(s0b, qh[1], bl1[0], bl1[1]);
            MMA_BF16(s1a, qh[0], bh0[2], bh0[3]);
            MMA_BF16(s1b, qh[1], bh1[2], bh1[3]);
            MMA_BF16(s1a, ql[0], bh0[2], bh0[3]);
            MMA_BF16(s1b, ql[1], bh1[2], bh1[3]);
            MMA_BF16(s1a, qh[0], bl0[2], bl0[3]);
            MMA_BF16(s1b, qh[1], bl1[2], bl1[3]);

            float s0v[4], s1v[4];
            #pragma unroll
            for (int i = 0; i < 4; i++) {
                s0v[i] = exp2f(s0a[i] + s0b[i]);
                s1v[i] = exp2f(s1a[i] + s1b[i]);
            }
            rs0 += s0v[0] + s0v[1] + s1v[0] + s1v[1];
            rs1 += s0v[2] + s0v[3] + s1v[2] + s1v[3];

            uint32_t ah[4], al[4];
            pack_hilo(s0v[0], s0v[1], ah[0], al[0]);
            pack_hilo(s0v[2], s0v[3], ah[1], al[1]);
            pack_hilo(s1v[0], s1v[1], ah[2], al[2]);
            pack_hilo(s1v[2], s1v[3], ah[3], al[3]);

            MMA_BF16(oacc[0], ah, vh0[0], vh0[1]);
            MMA_BF16(oacc[1], ah, vh0[2], vh0[3]);
            MMA_BF16(oacc[2], ah, vh1[0], vh1[1]);
            MMA_BF16(oacc[3], ah, vh1[2], vh1[3]);
            MMA_BF16(oacc[0], al, vh0[0], vh0[1]);
            MMA_BF16(oacc[1], al, vh0[2], vh0[3]);
            MMA_BF16(oacc[2], al, vh1[0], vh1[1]);
            MMA_BF16(oacc[3], al, vh1[2], vh1[3]);
            MMA_BF16(oacc[0], ah, vl0[0], vl0[1]);
            MMA_BF16(oacc[1], ah, vl0[2], vl0[3]);
            MMA_BF16(oacc[2], ah, vl1[0], vl1[1]);
            MMA_BF16(oacc[3], ah, vl1[2], vl1[3]);
        }
        __syncthreads();
    }

    // epilogue: reduce sums, transpose O through smem, write [c][p] coalesced
    rs0 += __shfl_xor_sync(0xffffffffu, rs0, 1);
    rs0 += __shfl_xor_sync(0xffffffffu, rs0, 2);
    rs1 += __shfl_xor_sync(0xffffffffu, rs1, 1);
    rs1 += __shfl_xor_sync(0xffffffffu, rs1, 2);
    const float inv0 = 1.f / rs0;
    const float inv1 = 1.f / rs1;

    float* Osm = (float*)smA;               // [32 d][260 q-pad] = 33.3 KB
    const int qloc = 16 * w + g;
    #pragma unroll
    for (int nv = 0; nv < 4; nv++) {
        #pragma unroll
        for (int cc = 0; cc < 2; cc++) {
            int d = 8 * nv + 2 * c + cc;
            Osm[d * 260 + qloc]     = oacc[nv][cc]     * inv0;
            Osm[d * 260 + qloc + 8] = oacc[nv][2 + cc] * inv1;
        }
    }
    __syncthreads();
    {
        int d  = tid >> 4;            // 0..31
        int qc = (tid & 15) * 16;     // 0..240
        __nv_bfloat16 hbuf[16], lbuf[16];
        #pragma unroll
        for (int i = 0; i < 16; i++)
            split1(Osm[d * 260 + qc + i], hbuf[i], lbuf[i]);
        size_t dst = (size_t)(b * CH + m * HD + d) * NTOK + q0 + qc;
        *(uint4*)&g_Oh[dst]     = *(uint4*)&hbuf[0];
        *(uint4*)&g_Oh[dst + 8] = *(uint4*)&hbuf[8];
        *(uint4*)&g_Ol[dst]     = *(uint4*)&lbuf[0];
        *(uint4*)&g_Ol[dst + 8] = *(uint4*)&lbuf[8];
    }
}

// ---------------------------------------------------------------------------
extern "C" void kernel_launch(void* const* d_in, const int* in_sizes, int n_in,
                              void* d_out, int out_size)
{
    (void)in_sizes; (void)n_in; (void)out_size;
    const float* x    = (const float*)d_in[0];
    const float* Wqkv = (const float*)d_in[1];
    const float* bqkv = (const float*)d_in[2];
    const float* W0   = (const float*)d_in[3];
    const float* b0   = (const float*)d_in[4];
    float* out = (float*)d_out;

    cudaFuncSetAttribute(attn_kernel, cudaFuncAttributeMaxDynamicSharedMemorySize, ATTN_SMEM);
    cudaFuncSetAttribute(qkv_kernel,  cudaFuncAttributeMaxDynamicSharedMemorySize, GEMM_SMEM);
    cudaFuncSetAttribute(proj_kernel, cudaFuncAttributeMaxDynamicSharedMemorySize, GEMM_SMEM);

    split_x_kernel<<<BATCH * CH * NTOK / 1024, 256>>>(x);
    split_w_kernel<<<(3 * CH * CH + CH * CH) / 1024, 256>>>(Wqkv, W0);
    qkv_kernel<<<dim3(NTOK / 128, (3 * CH) / 64, BATCH), 256, GEMM_SMEM>>>(bqkv);
    attn_kernel<<<dim3(NTOK / 256, BATCH * NH), 512, ATTN_SMEM>>>();
    proj_kernel<<<dim3(NTOK / 128, CH / 64, BATCH), 256, GEMM_SMEM>>>(b0, out);
}